// round 1
// baseline (speedup 1.0000x reference)
#include <cuda_runtime.h>
#include <math_constants.h>

#define BATCH 8
#define HH 224
#define WW 224
#define OH 223
#define OW 223
#define PI_F 3.14159265358979323846f

// per-batch min/max as order-preserving uint keys
__device__ unsigned g_minkey[BATCH];
__device__ unsigned g_maxkey[BATCH];

__device__ __forceinline__ unsigned f2key(float f) {
    unsigned u = __float_as_uint(f);
    return (u & 0x80000000u) ? ~u : (u | 0x80000000u);
}
__device__ __forceinline__ float key2f(unsigned k) {
    unsigned u = (k & 0x80000000u) ? (k & 0x7FFFFFFFu) : ~k;
    return __uint_as_float(u);
}

__global__ void reset_kernel() {
    int i = threadIdx.x;
    if (i < BATCH) {
        g_minkey[i] = 0xFFFFFFFFu;
        g_maxkey[i] = 0u;
    }
}

__global__ void minmax_kernel(const float* __restrict__ x) {
    const int b = blockIdx.y;
    const float4* xb = (const float4*)(x + (size_t)b * 2 * HH * WW);
    const int nvec = 2 * HH * WW / 4;  // 50176
    float lmin = CUDART_INF_F;
    float lmax = -CUDART_INF_F;
    for (int i = blockIdx.x * blockDim.x + threadIdx.x; i < nvec;
         i += gridDim.x * blockDim.x) {
        float4 v = xb[i];
        lmin = fminf(lmin, fminf(fminf(v.x, v.y), fminf(v.z, v.w)));
        lmax = fmaxf(lmax, fmaxf(fmaxf(v.x, v.y), fmaxf(v.z, v.w)));
    }
    // warp reduce
    for (int off = 16; off > 0; off >>= 1) {
        lmin = fminf(lmin, __shfl_xor_sync(0xFFFFFFFFu, lmin, off));
        lmax = fmaxf(lmax, __shfl_xor_sync(0xFFFFFFFFu, lmax, off));
    }
    __shared__ float smin[8], smax[8];
    int wid = threadIdx.x >> 5, lid = threadIdx.x & 31;
    if (lid == 0) { smin[wid] = lmin; smax[wid] = lmax; }
    __syncthreads();
    if (threadIdx.x == 0) {
        int nw = blockDim.x >> 5;
        for (int i = 1; i < nw; i++) {
            lmin = fminf(lmin, smin[i]);
            lmax = fmaxf(lmax, smax[i]);
        }
        atomicMin(&g_minkey[b], f2key(lmin));
        atomicMax(&g_maxkey[b], f2key(lmax));
    }
}

// Main fused kernel: 32x32 output tile per block, 256 threads.
// smem holds per-pixel t = cos(a)*cos(b), s = sin(a) for a 33x33 halo tile.
__global__ void __launch_bounds__(256)
quanv_kernel(const float* __restrict__ x, const float* __restrict__ wts,
             float* __restrict__ out) {
    __shared__ float sT[33 * 33];
    __shared__ float sS[33 * 33];
    __shared__ float s_cw[4], s_sw[4];

    const int b = blockIdx.z;
    const int r0 = blockIdx.y * 32;
    const int c0 = blockIdx.x * 32;
    const int tid = threadIdx.x;

    if (tid < 4) {
        float w = wts[tid];
        s_cw[tid] = cosf(w);
        s_sw[tid] = sinf(w);
    }

    const float fmn = key2f(g_minkey[b]);
    const float fmx = key2f(g_maxkey[b]);
    const float scale = PI_F / (fmx - fmn + 1e-8f);

    const float* x0 = x + (size_t)b * 2 * HH * WW;
    const float* x1 = x0 + HH * WW;

    #pragma unroll
    for (int i = tid; i < 33 * 33; i += 256) {
        int rr = i / 33, cc = i - rr * 33;
        int r = min(r0 + rr, HH - 1);
        int c = min(c0 + cc, WW - 1);
        float a = (x0[r * WW + c] - fmn) * scale;
        float bb = (x1[r * WW + c] - fmn) * scale;
        float sa, ca;
        __sincosf(a, &sa, &ca);
        sT[i] = ca * __cosf(bb);
        sS[i] = sa;
    }
    __syncthreads();

    const float cw0 = s_cw[0], sw0 = s_sw[0];
    const float cw1 = s_cw[1], sw1 = s_sw[1];
    const float cw2 = s_cw[2], sw2 = s_sw[2];
    const float cw3 = s_cw[3], sw3 = s_sw[3];

    const int tx = tid & 31;
    const int ty = tid >> 5;  // 0..7, each handles 4 rows

    const size_t plane = (size_t)OH * OW;
    float* ob = out + (size_t)b * 4 * plane;

    #pragma unroll
    for (int k = 0; k < 4; k++) {
        int ly = ty * 4 + k;       // local output row 0..31
        int oh = r0 + ly;
        int ow = c0 + tx;
        if (oh < OH && ow < OW) {
            int p = ly * 33 + tx;
            // qubit i at (kh,kw)=(i>>1, i&1): z_i = cw_i*t - sw_i*s
            float z0 = fmaf(cw0, sT[p],      -sw0 * sS[p]);
            float z1 = fmaf(cw1, sT[p + 1],  -sw1 * sS[p + 1]);
            float z2 = fmaf(cw2, sT[p + 33], -sw2 * sS[p + 33]);
            float z3 = fmaf(cw3, sT[p + 34], -sw3 * sS[p + 34]);
            float z01 = z0 * z1;
            float z23 = z2 * z3;
            size_t o = (size_t)oh * OW + ow;
            ob[0 * plane + o] = z1 * z23;   // <Z0> = z1 z2 z3
            ob[1 * plane + o] = z01;        // <Z1> = z0 z1
            ob[2 * plane + o] = z01 * z2;   // <Z2> = z0 z1 z2
            ob[3 * plane + o] = z01 * z23;  // <Z3> = z0 z1 z2 z3
        }
    }
}

extern "C" void kernel_launch(void* const* d_in, const int* in_sizes, int n_in,
                              void* d_out, int out_size) {
    const float* x = (const float*)d_in[0];        // [8,2,224,224]
    const float* wts = (const float*)d_in[1];      // [1,4]
    float* out = (float*)d_out;                    // [8,4,223,223]

    reset_kernel<<<1, 32>>>();
    dim3 mm_grid(32, BATCH);
    minmax_kernel<<<mm_grid, 256>>>(x);
    dim3 grid((OW + 31) / 32, (OH + 31) / 32, BATCH);  // 7 x 7 x 8
    quanv_kernel<<<grid, 256>>>(x, wts, out);
}

// round 2
// speedup vs baseline: 1.2362x; 1.2362x over previous
#include <cuda_runtime.h>
#include <math_constants.h>

#define BATCH 8
#define HH 224
#define WW 224
#define OH 223
#define OW 223
#define NBLK 49          // 7x7 blocks per batch
#define PI_F 3.14159265358979323846f

// Per-(batch,block) min/max partials — written unconditionally every launch,
// so no reset kernel is needed (graph-replay safe).
__device__ float g_pmin[BATCH][NBLK];
__device__ float g_pmax[BATCH][NBLK];
// Monotonic ticket counter per batch (never reset; wrap-safe comparison).
__device__ unsigned g_cnt[BATCH];

__global__ void __launch_bounds__(256)
quanv_fused(const float* __restrict__ x, const float* __restrict__ wts,
            float* __restrict__ out) {
    __shared__ float sT[33 * 33];
    __shared__ float sS[33 * 33];
    __shared__ float sred[16];          // 8 warp mins + 8 warp maxs
    __shared__ float sP[2 * NBLK];      // staged partials
    __shared__ float s_fmn, s_scale;
    __shared__ float s_cw[4], s_sw[4];

    const int b   = blockIdx.z;
    const int blk = blockIdx.y * 7 + blockIdx.x;   // 0..48 within batch
    const int tid = threadIdx.x;
    const int r0  = blockIdx.y * 32;
    const int c0  = blockIdx.x * 32;

    if (tid < 4) {
        float w = wts[tid];
        s_cw[tid] = cosf(w);
        s_sw[tid] = sinf(w);
    }

    // ---- Phase 1: local min/max over this block's 1/49 slice of the batch ----
    const float* xb = x + (size_t)b * 2 * HH * WW;
    const float4* xv = (const float4*)xb;          // 25088 float4 per batch
    float lmin = CUDART_INF_F, lmax = -CUDART_INF_F;
    #pragma unroll
    for (int j = 0; j < 2; j++) {                   // 49 * 512 = 25088 exactly
        float4 v = xv[blk * 512 + j * 256 + tid];
        lmin = fminf(lmin, fminf(fminf(v.x, v.y), fminf(v.z, v.w)));
        lmax = fmaxf(lmax, fmaxf(fmaxf(v.x, v.y), fmaxf(v.z, v.w)));
    }
    #pragma unroll
    for (int off = 16; off > 0; off >>= 1) {
        lmin = fminf(lmin, __shfl_xor_sync(0xFFFFFFFFu, lmin, off));
        lmax = fmaxf(lmax, __shfl_xor_sync(0xFFFFFFFFu, lmax, off));
    }
    if ((tid & 31) == 0) { sred[tid >> 5] = lmin; sred[8 + (tid >> 5)] = lmax; }

    // ---- Prefetch raw tile pixels into registers (latency hides behind barrier) ----
    const float* x0 = xb;
    const float* x1 = xb + HH * WW;
    float ra[5], rb[5];
    #pragma unroll
    for (int j = 0; j < 5; j++) {
        int i = tid + j * 256;
        if (i < 33 * 33) {
            int rr = i / 33, cc = i - rr * 33;
            int r = min(r0 + rr, HH - 1);
            int c = min(c0 + cc, WW - 1);
            ra[j] = __ldg(x0 + r * WW + c);
            rb[j] = __ldg(x1 + r * WW + c);
        }
    }

    __syncthreads();
    // ---- Publish partial, per-batch software barrier (thread 0) ----
    if (tid == 0) {
        float m0 = sred[0], m1 = sred[8];
        #pragma unroll
        for (int i = 1; i < 8; i++) {
            m0 = fminf(m0, sred[i]);
            m1 = fmaxf(m1, sred[8 + i]);
        }
        __stcg(&g_pmin[b][blk], m0);
        __stcg(&g_pmax[b][blk], m1);
        __threadfence();                            // release partials
        unsigned ticket = atomicAdd(&g_cnt[b], 1u);
        unsigned target = ticket - (ticket % NBLK) + NBLK;  // end of this generation
        while ((int)(atomicAdd(&g_cnt[b], 0u) - target) < 0) { }
    }
    __syncthreads();

    // ---- Reduce the 49 partials (L2-coherent loads) ----
    if (tid < NBLK) {
        sP[tid]        = __ldcg(&g_pmin[b][tid]);
        sP[NBLK + tid] = __ldcg(&g_pmax[b][tid]);
    }
    __syncthreads();
    if (tid == 0) {
        float m0 = sP[0], m1 = sP[NBLK];
        #pragma unroll
        for (int i = 1; i < NBLK; i++) {
            m0 = fminf(m0, sP[i]);
            m1 = fmaxf(m1, sP[NBLK + i]);
        }
        s_fmn = m0;
        s_scale = PI_F / (m1 - m0 + 1e-8f);
    }
    __syncthreads();

    // ---- Transform tile: t = cos(a)cos(b), s = sin(a) ----
    const float fmn = s_fmn, scale = s_scale;
    #pragma unroll
    for (int j = 0; j < 5; j++) {
        int i = tid + j * 256;
        if (i < 33 * 33) {
            float a  = (ra[j] - fmn) * scale;
            float bb = (rb[j] - fmn) * scale;
            float sa, ca;
            __sincosf(a, &sa, &ca);
            sT[i] = ca * __cosf(bb);
            sS[i] = sa;
        }
    }
    __syncthreads();

    // ---- Output stage: z_i = cw_i*t - sw_i*s at 4 corners, parity products ----
    const float cw0 = s_cw[0], sw0 = s_sw[0];
    const float cw1 = s_cw[1], sw1 = s_sw[1];
    const float cw2 = s_cw[2], sw2 = s_sw[2];
    const float cw3 = s_cw[3], sw3 = s_sw[3];

    const int tx = tid & 31;
    const int ty = tid >> 5;
    const size_t plane = (size_t)OH * OW;
    float* ob = out + (size_t)b * 4 * plane;

    #pragma unroll
    for (int k = 0; k < 4; k++) {
        int ly = ty * 4 + k;
        int oh = r0 + ly;
        int ow = c0 + tx;
        if (oh < OH && ow < OW) {
            int p = ly * 33 + tx;
            float z0 = fmaf(cw0, sT[p],      -sw0 * sS[p]);
            float z1 = fmaf(cw1, sT[p + 1],  -sw1 * sS[p + 1]);
            float z2 = fmaf(cw2, sT[p + 33], -sw2 * sS[p + 33]);
            float z3 = fmaf(cw3, sT[p + 34], -sw3 * sS[p + 34]);
            float z01 = z0 * z1;
            float z23 = z2 * z3;
            size_t o = (size_t)oh * OW + ow;
            ob[0 * plane + o] = z1 * z23;   // <Z0> = z1 z2 z3
            ob[1 * plane + o] = z01;        // <Z1> = z0 z1
            ob[2 * plane + o] = z01 * z2;   // <Z2> = z0 z1 z2
            ob[3 * plane + o] = z01 * z23;  // <Z3> = z0 z1 z2 z3
        }
    }
}

extern "C" void kernel_launch(void* const* d_in, const int* in_sizes, int n_in,
                              void* d_out, int out_size) {
    const float* x   = (const float*)d_in[0];   // [8,2,224,224]
    const float* wts = (const float*)d_in[1];   // [1,4]
    float* out = (float*)d_out;                 // [8,4,223,223]

    dim3 grid(7, 7, BATCH);                     // 392 blocks, all co-resident
    quanv_fused<<<grid, 256>>>(x, wts, out);
}